// round 2
// baseline (speedup 1.0000x reference)
#include <cuda_runtime.h>
#include <cuda_bf16.h>
#include <mma.h>

using namespace nvcuda;

#define N_TOT 8192
#define BSZ   4096
#define D     256
#define TILE  128
#define LDS   264   // smem row stride (bf16 elems), padded: 528B rows -> no ldmatrix bank conflicts
#define LDC   132   // smem C row stride (f32 elems)
#define INV_T 14.285714285714286f
#define EPS_  1e-7f

// Scratch (device globals: no allocation allowed in kernel_launch)
__device__ __nv_bfloat16 g_F[N_TOT * D];   // view-permuted bf16 features
__device__ float g_pos[N_TOT];             // sum over label-matching j != i of exp(dot/T)
__device__ float g_tot[N_TOT];             // sum over all j != i of exp(dot/T)

// ---------------------------------------------------------------------------
// Kernel 1: repack features [bsz, n_views, d] -> contrast_feature rows [n, d]
// (row i = view i/4096, batch i%4096), convert to bf16, zero accumulators.
// ---------------------------------------------------------------------------
__global__ void prep_kernel(const float* __restrict__ feats) {
    int i = blockIdx.x;       // 0..8191
    int k = threadIdx.x;      // 0..255
    int v = i >> 12;
    int b = i & (BSZ - 1);
    g_F[i * D + k] = __float2bfloat16(feats[(b * 2 + v) * D + k]);
    if (k == 0) { g_pos[i] = 0.f; g_tot[i] = 0.f; }
}

// ---------------------------------------------------------------------------
// Kernel 2: tile (128x128) of S = F F^T via wmma bf16, fused epilogue:
//   e = exp(S/T); tot_i += e (j!=i); pos_i += e (labels match, j!=i)
// ---------------------------------------------------------------------------
extern __shared__ char smem_raw[];

__global__ void gemm_kernel(const int* __restrict__ labels) {
    __nv_bfloat16* Ash = (__nv_bfloat16*)smem_raw;
    __nv_bfloat16* Bsh = Ash + TILE * LDS;
    float*         Csh = (float*)smem_raw;      // overlays A/B after GEMM

    __shared__ int lblA[TILE];
    __shared__ int lblB[TILE];

    const int i0 = blockIdx.y * TILE;
    const int j0 = blockIdx.x * TILE;
    const int tid  = threadIdx.x;
    const int wid  = tid >> 5;
    const int lane = tid & 31;

    if (tid < TILE) {
        lblA[tid] = labels[(i0 + tid) & (BSZ - 1)];
        lblB[tid] = labels[(j0 + tid) & (BSZ - 1)];
    }

    // Stage both full tiles (rows are contiguous 512B in global -> pure vector copy)
    const uint4* srcA = (const uint4*)(g_F + (size_t)i0 * D);
    const uint4* srcB = (const uint4*)(g_F + (size_t)j0 * D);
    for (int idx = tid; idx < TILE * 32; idx += 256) {   // 32 uint4 per 256-elem row
        int r = idx >> 5, c = idx & 31;
        ((uint4*)(Ash + r * LDS))[c] = srcA[r * 32 + c];
        ((uint4*)(Bsh + r * LDS))[c] = srcB[r * 32 + c];
    }
    __syncthreads();

    // Warp tiling: 8 warps -> (4 row-groups x 2 col-groups); each warp 32x64 out
    const int wm = wid & 3;      // 0..3
    const int wn = wid >> 2;     // 0..1

    wmma::fragment<wmma::accumulator, 16, 16, 16, float> cf[2][4];
    #pragma unroll
    for (int a = 0; a < 2; a++)
        #pragma unroll
        for (int b2 = 0; b2 < 4; b2++)
            wmma::fill_fragment(cf[a][b2], 0.0f);

    #pragma unroll
    for (int k0 = 0; k0 < D; k0 += 16) {
        wmma::fragment<wmma::matrix_a, 16, 16, 16, __nv_bfloat16, wmma::row_major> af[2];
        wmma::fragment<wmma::matrix_b, 16, 16, 16, __nv_bfloat16, wmma::col_major> bf[4];
        #pragma unroll
        for (int a = 0; a < 2; a++)
            wmma::load_matrix_sync(af[a], Ash + (wm * 32 + a * 16) * LDS + k0, LDS);
        #pragma unroll
        for (int b2 = 0; b2 < 4; b2++)
            wmma::load_matrix_sync(bf[b2], Bsh + (wn * 64 + b2 * 16) * LDS + k0, LDS);
        #pragma unroll
        for (int a = 0; a < 2; a++)
            #pragma unroll
            for (int b2 = 0; b2 < 4; b2++)
                wmma::mma_sync(cf[a][b2], af[a], bf[b2], cf[a][b2]);
    }
    __syncthreads();   // A/B smem no longer needed; safe to overlay C

    #pragma unroll
    for (int a = 0; a < 2; a++)
        #pragma unroll
        for (int b2 = 0; b2 < 4; b2++)
            wmma::store_matrix_sync(Csh + (wm * 32 + a * 16) * LDC + wn * 64 + b2 * 16,
                                    cf[a][b2], LDC, wmma::mem_row_major);
    __syncthreads();

    // Fused epilogue: warp wid reduces rows [wid*16, wid*16+16)
    #pragma unroll
    for (int rr = 0; rr < 16; rr++) {
        const int r  = wid * 16 + rr;
        const int i  = i0 + r;
        const int li = lblA[r];
        float tot = 0.f, pos = 0.f;
        #pragma unroll
        for (int ci = 0; ci < TILE; ci += 32) {
            const int c = ci + lane;
            const int j = j0 + c;
            if (i != j) {  // drop self-contrast (diagonal tiles only)
                float e = __expf(Csh[r * LDC + c] * INV_T);
                tot += e;
                if (lblB[c] == li) pos += e;
            }
        }
        #pragma unroll
        for (int off = 16; off; off >>= 1) {
            tot += __shfl_down_sync(0xffffffffu, tot, off);
            pos += __shfl_down_sync(0xffffffffu, pos, off);
        }
        if (lane == 0) {
            atomicAdd(&g_tot[i], tot);
            atomicAdd(&g_pos[i], pos);
        }
    }
}

// ---------------------------------------------------------------------------
// Kernel 3: loss = -mean(log((pos + eps*tot) / tot))
// ---------------------------------------------------------------------------
__global__ void finalize_kernel(float* __restrict__ out) {
    __shared__ float red[256];
    float s = 0.f;
    for (int i = threadIdx.x; i < N_TOT; i += 256) {
        float t = g_tot[i];
        float p = g_pos[i] + EPS_ * t;
        s += logf(p / t);
    }
    red[threadIdx.x] = s;
    __syncthreads();
    for (int st = 128; st; st >>= 1) {
        if (threadIdx.x < st) red[threadIdx.x] += red[threadIdx.x + st];
        __syncthreads();
    }
    if (threadIdx.x == 0) out[0] = -red[0] / (float)N_TOT;
}

// ---------------------------------------------------------------------------
extern "C" void kernel_launch(void* const* d_in, const int* in_sizes, int n_in,
                              void* d_out, int out_size) {
    const float* feats  = (const float*)d_in[0];
    const int*   labels = (const int*)d_in[1];
    float*       out    = (float*)d_out;

    prep_kernel<<<N_TOT, D>>>(feats);

    const size_t smem = (size_t)2 * TILE * LDS * sizeof(__nv_bfloat16);  // 135168 B
    cudaFuncSetAttribute(gemm_kernel, cudaFuncAttributeMaxDynamicSharedMemorySize, (int)smem);
    gemm_kernel<<<dim3(N_TOT / TILE, N_TOT / TILE), 256, smem>>>(labels);

    finalize_kernel<<<1, 256>>>(out);
}

// round 4
// speedup vs baseline: 2.6614x; 2.6614x over previous
#include <cuda_runtime.h>
#include <cuda_bf16.h>
#include <cstdint>

#define N_TOT 8192
#define BSZ   4096
#define D     256
#define TILE  128
#define INV_T 14.285714285714286f
#define EPS_  1e-7f
#define STRIPS 64
#define JSPLIT 2
#define TPC    32          // j-tiles per CTA

// smem layout: A strip (64KB) + 2 x (B tile 64KB + 512B labels)
#define A_BYTES   65536
#define BUF_BYTES (65536 + 512)
#define OFF_B(b)   (A_BYTES + (b) * BUF_BYTES)
#define OFF_LBL(b) (OFF_B(b) + 65536)
#define SMEM_TOTAL (A_BYTES + 2 * BUF_BYTES)   // 197632 B

__device__ __nv_bfloat16 g_F[N_TOT * D];
__device__ float g_pos[N_TOT];
__device__ float g_tot[N_TOT];

// ---------------------------------------------------------------------------
// helpers
// ---------------------------------------------------------------------------
__device__ __forceinline__ uint32_t smem_u32(const void* p) {
    uint32_t a;
    asm("{ .reg .u64 t; cvta.to.shared.u64 t, %1; cvt.u32.u64 %0, t; }" : "=r"(a) : "l"(p));
    return a;
}
__device__ __forceinline__ void cp16(uint32_t s, const void* g) {
    asm volatile("cp.async.cg.shared.global [%0], [%1], 16;" :: "r"(s), "l"(g) : "memory");
}
__device__ __forceinline__ void cp_commit() {
    asm volatile("cp.async.commit_group;" ::: "memory");
}
template <int N> __device__ __forceinline__ void cp_wait() {
    asm volatile("cp.async.wait_group %0;" :: "n"(N) : "memory");
}
__device__ __forceinline__ void ldsm4(uint32_t* r, uint32_t addr) {
    asm volatile("ldmatrix.sync.aligned.m8n8.x4.shared.b16 {%0,%1,%2,%3}, [%4];"
                 : "=r"(r[0]), "=r"(r[1]), "=r"(r[2]), "=r"(r[3]) : "r"(addr));
}
__device__ __forceinline__ void ldsm2(uint32_t* r, uint32_t addr) {
    asm volatile("ldmatrix.sync.aligned.m8n8.x2.shared.b16 {%0,%1}, [%2];"
                 : "=r"(r[0]), "=r"(r[1]) : "r"(addr));
}
__device__ __forceinline__ void mma16816(float* c, const uint32_t* a, const uint32_t* b) {
    asm volatile(
        "mma.sync.aligned.m16n8k16.row.col.f32.bf16.bf16.f32 "
        "{%0,%1,%2,%3}, {%4,%5,%6,%7}, {%8,%9}, {%0,%1,%2,%3};"
        : "+f"(c[0]), "+f"(c[1]), "+f"(c[2]), "+f"(c[3])
        : "r"(a[0]), "r"(a[1]), "r"(a[2]), "r"(a[3]), "r"(b[0]), "r"(b[1]));
}

// stage 128x256 bf16 tile; XOR swizzle: 16B chunk c of row r -> c ^ (r&7)
__device__ __forceinline__ void cp_tile(uint32_t dst, const __nv_bfloat16* src, int tid) {
    const char* s = (const char*)src;
    #pragma unroll
    for (int it = 0; it < 16; it++) {
        int idx = it * 256 + tid;            // 0..4095 16B chunks
        int r = idx >> 5, c = idx & 31;
        uint32_t d = dst + r * 512 + ((c ^ (r & 7)) << 4);
        cp16(d, s + idx * 16);
    }
}

// ---------------------------------------------------------------------------
// Kernel 1: repack fp32 [bsz,2,d] -> bf16 contrast rows [n,d]; zero accums
// ---------------------------------------------------------------------------
__global__ void prep_kernel(const float* __restrict__ feats) {
    int i = blockIdx.x;
    int k = threadIdx.x;                     // 0..127, 2 elems each
    int v = i >> 12;
    int b = i & (BSZ - 1);
    float2 f = ((const float2*)(feats + (size_t)(b * 2 + v) * D))[k];
    __nv_bfloat162 h;
    h.x = __float2bfloat16(f.x);
    h.y = __float2bfloat16(f.y);
    ((__nv_bfloat162*)(g_F + (size_t)i * D))[k] = h;
    if (k == 0) { g_pos[i] = 0.f; g_tot[i] = 0.f; }
}

// ---------------------------------------------------------------------------
// Kernel 2: persistent-strip GEMM (mma.sync bf16) with register epilogue
// ---------------------------------------------------------------------------
extern __shared__ char smem[];

__global__ void __launch_bounds__(256, 1)
gemm_kernel(const int* __restrict__ labels) {
    const uint32_t sb = smem_u32(smem);
    const int tid  = threadIdx.x;
    const int wid  = tid >> 5;
    const int lane = tid & 31;
    const int strip = blockIdx.x >> 1;
    const int half  = blockIdx.x & 1;
    const int i0 = strip * TILE;
    const int wm = wid >> 2;                 // 0..1  (64-row group)
    const int wn = wid & 3;                  // 0..3  (32-col group)

    // per-thread row labels + strip accumulators (rows fixed for whole strip)
    int   li[4][2];
    float atot[4][2], apos[4][2];
    #pragma unroll
    for (int mf = 0; mf < 4; mf++)
        #pragma unroll
        for (int h = 0; h < 2; h++) {
            int r = i0 + wm * 64 + mf * 16 + (lane >> 2) + h * 8;
            li[mf][h] = labels[r & (BSZ - 1)];
            atot[mf][h] = 0.f; apos[mf][h] = 0.f;
        }

    // group0: A strip + B0 + labels0
    cp_tile(sb, g_F + (size_t)i0 * D, tid);
    {
        int j0 = half * TPC * TILE;
        cp_tile(sb + OFF_B(0), g_F + (size_t)j0 * D, tid);
        if (tid < 32) cp16(sb + OFF_LBL(0) + tid * 16, labels + (j0 & (BSZ - 1)) + tid * 4);
    }
    cp_commit();

    // ldmatrix per-lane address bases
    const int arow  = wm * 64 + (lane & 7) + ((lane >> 3) & 1) * 8;  // + mf*16
    const uint32_t a_base = sb + arow * 512;
    const int a_xor = arow & 7;
    const int a_hi  = lane >> 4;
    const int lb16  = lane & 15;
    const int b_hi  = (lb16 >> 3) & 1;
    const int brow_l = lb16 & 7;

    for (int t = 0; t < TPC; t++) {
        const int buf = t & 1;
        if (t + 1 < TPC) {
            int j0n = (half * TPC + t + 1) * TILE;
            cp_tile(sb + OFF_B(buf ^ 1), g_F + (size_t)j0n * D, tid);
            if (tid < 32) cp16(sb + OFF_LBL(buf ^ 1) + tid * 16,
                               labels + (j0n & (BSZ - 1)) + tid * 4);
            cp_commit();
            cp_wait<1>();
        } else {
            cp_wait<0>();
        }
        __syncthreads();                     // tile t (and A) visible to all

        const uint32_t b_s = sb + OFF_B(buf);
        float c[4][4][4];
        #pragma unroll
        for (int mf = 0; mf < 4; mf++)
            #pragma unroll
            for (int nf = 0; nf < 4; nf++)
                #pragma unroll
                for (int q = 0; q < 4; q++) c[mf][nf][q] = 0.f;

        #pragma unroll
        for (int kc = 0; kc < 16; kc++) {
            uint32_t af[4][4], bf[4][2];
            #pragma unroll
            for (int mf = 0; mf < 4; mf++) {
                uint32_t addr = a_base + mf * (16 * 512)
                              + ((((kc << 1) + a_hi) ^ a_xor) << 4);
                ldsm4(af[mf], addr);
            }
            #pragma unroll
            for (int nf = 0; nf < 4; nf++) {
                int brow = wn * 32 + nf * 8 + brow_l;
                uint32_t addr = b_s + brow * 512
                              + ((((kc << 1) + b_hi) ^ (brow & 7)) << 4);
                ldsm2(bf[nf], addr);
            }
            #pragma unroll
            for (int mf = 0; mf < 4; mf++)
                #pragma unroll
                for (int nf = 0; nf < 4; nf++)
                    mma16816(c[mf][nf], af[mf], bf[nf]);
        }

        // fused register epilogue
        const int j0 = (half * TPC + t) * TILE;
        const int* lbl = (const int*)(smem + OFF_LBL(buf));
        const bool diag = (j0 == i0);
        #pragma unroll
        for (int mf = 0; mf < 4; mf++) {
            #pragma unroll
            for (int nf = 0; nf < 4; nf++) {
                const int col0 = wn * 32 + nf * 8 + (lane & 3) * 2;
                const int l0 = lbl[col0], l1 = lbl[col0 + 1];
                float e00 = __expf(c[mf][nf][0] * INV_T);
                float e01 = __expf(c[mf][nf][1] * INV_T);
                float e10 = __expf(c[mf][nf][2] * INV_T);
                float e11 = __expf(c[mf][nf][3] * INV_T);
                if (diag) {
                    const int r0 = wm * 64 + mf * 16 + (lane >> 2);
                    const int r1 = r0 + 8;
                    if (r0 == col0)     e00 = 0.f;
                    if (r0 == col0 + 1) e01 = 0.f;
                    if (r1 == col0)     e10 = 0.f;
                    if (r1 == col0 + 1) e11 = 0.f;
                }
                atot[mf][0] += e00 + e01;
                atot[mf][1] += e10 + e11;
                apos[mf][0] += (l0 == li[mf][0] ? e00 : 0.f) + (l1 == li[mf][0] ? e01 : 0.f);
                apos[mf][1] += (l0 == li[mf][1] ? e10 : 0.f) + (l1 == li[mf][1] ? e11 : 0.f);
            }
        }
        __syncthreads();                     // all reads of buf done before overwrite
    }

    // quad reduction (lanes sharing l>>2 own the same rows) + one atomic pair/row
    #pragma unroll
    for (int mf = 0; mf < 4; mf++)
        #pragma unroll
        for (int h = 0; h < 2; h++) {
            float tt = atot[mf][h], pp = apos[mf][h];
            tt += __shfl_xor_sync(0xffffffffu, tt, 1);
            tt += __shfl_xor_sync(0xffffffffu, tt, 2);
            pp += __shfl_xor_sync(0xffffffffu, pp, 1);
            pp += __shfl_xor_sync(0xffffffffu, pp, 2);
            if ((lane & 3) == mf) {
                int r = i0 + wm * 64 + mf * 16 + (lane >> 2) + h * 8;
                atomicAdd(&g_tot[r], tt);
                atomicAdd(&g_pos[r], pp);
            }
        }
}

// ---------------------------------------------------------------------------
// Kernel 3: loss = -mean(log((pos + eps*tot)/tot))
// ---------------------------------------------------------------------------
__global__ void finalize_kernel(float* __restrict__ out) {
    __shared__ float red[256];
    float s = 0.f;
    for (int i = threadIdx.x; i < N_TOT; i += 256) {
        float t = g_tot[i];
        float p = g_pos[i] + EPS_ * t;
        s += logf(p / t);
    }
    red[threadIdx.x] = s;
    __syncthreads();
    for (int st = 128; st; st >>= 1) {
        if (threadIdx.x < st) red[threadIdx.x] += red[threadIdx.x + st];
        __syncthreads();
    }
    if (threadIdx.x == 0) out[0] = -red[0] / (float)N_TOT;
}

// ---------------------------------------------------------------------------
extern "C" void kernel_launch(void* const* d_in, const int* in_sizes, int n_in,
                              void* d_out, int out_size) {
    const float* feats  = (const float*)d_in[0];
    const int*   labels = (const int*)d_in[1];
    float*       out    = (float*)d_out;

    prep_kernel<<<N_TOT, D / 2>>>(feats);

    cudaFuncSetAttribute(gemm_kernel, cudaFuncAttributeMaxDynamicSharedMemorySize, SMEM_TOTAL);
    gemm_kernel<<<STRIPS * JSPLIT, 256, SMEM_TOTAL>>>(labels);

    finalize_kernel<<<1, 256>>>(out);
}